// round 16
// baseline (speedup 1.0000x reference)
#include <cuda_runtime.h>
#include <cuda_fp16.h>

// Encoding layer, fp16 tensor cores (mma.m16n8k16) + ldmatrix fragment loads.
// B=16, D=128, N=4096, K=32. One CTA = one (b, chunk) tile of 256 n.
// Single n-major X layout: GEMM1 A + GEMM2 B both via ldmatrix (B with .trans,
// transposing in the load -> no XsT copy). Smem ~57.6KB -> 3 CTAs/SM.
// fp16 scratch partials; PDL reduce, fixed-order (deterministic).

#define Dd   128
#define Kk   32
#define Bb   16
#define HWn  4096
#define TN   256
#define TIN  128
#define NT   2
#define CH   16
#define NTH  256
#define STH  136          // half-stride per row (272 B; rows cycle all 8 16B-groups)

#define XSH_OFF  0                       // [128][STH] n-major
#define CSH_OFF  (128*STH)               // [32][STH]
#define ASH_OFF  (160*STH)               // [32][STH]
#define HALF_TOT (192*STH)
#define X2P_OFF  0                       // floats: [8][128]
#define C2S_OFF  1024
#define RED_OFF  (C2S_OFF + 32)
#define ASUM_OFF (RED_OFF + 256)
#define FLT_TOT  (ASUM_OFF + 32)
#define SM_BYTES (HALF_TOT*2 + FLT_TOT*4)

__device__ __half2 g_scratchH[(size_t)Bb*CH*Kk*Dd/2];   // 2 MB fp16 partials

__device__ __forceinline__ void mma_f16(float* d,
    unsigned a0, unsigned a1, unsigned a2, unsigned a3, unsigned b0, unsigned b1) {
    asm("mma.sync.aligned.m16n8k16.row.col.f32.f16.f16.f32 "
        "{%0,%1,%2,%3}, {%4,%5,%6,%7}, {%8,%9}, {%0,%1,%2,%3};"
        : "+f"(d[0]), "+f"(d[1]), "+f"(d[2]), "+f"(d[3])
        : "r"(a0), "r"(a1), "r"(a2), "r"(a3), "r"(b0), "r"(b1));
}
__device__ __forceinline__ unsigned sptr(const void* p) {
    return (unsigned)__cvta_generic_to_shared(p);
}
__device__ __forceinline__ void ldm4(unsigned& r0, unsigned& r1,
                                     unsigned& r2, unsigned& r3, unsigned a) {
    asm volatile("ldmatrix.sync.aligned.m8n8.x4.shared.b16 {%0,%1,%2,%3}, [%4];"
                 : "=r"(r0), "=r"(r1), "=r"(r2), "=r"(r3) : "r"(a));
}
__device__ __forceinline__ void ldm4t(unsigned& r0, unsigned& r1,
                                      unsigned& r2, unsigned& r3, unsigned a) {
    asm volatile("ldmatrix.sync.aligned.m8n8.x4.trans.shared.b16 {%0,%1,%2,%3}, [%4];"
                 : "=r"(r0), "=r"(r1), "=r"(r2), "=r"(r3) : "r"(a));
}

__global__ void __launch_bounds__(NTH, 3) enc_main(
    const float* __restrict__ x,      // (B, D, HWn)
    const float* __restrict__ cw,     // (K, D)
    const float* __restrict__ scale)  // (K,)
{
    extern __shared__ __align__(16) char smraw[];
    __half* smh = (__half*)smraw;
    float*  smf = (float*)(smraw + HALF_TOT*2);

    const int tid = threadIdx.x;
    const int w   = tid >> 5;
    const int l   = tid & 31;
    const int lr  = l >> 2;
    const int lc  = l & 3;
    const int b     = blockIdx.y;
    const int chunk = blockIdx.x;
    const float* xb = x + (size_t)b * Dd * HWn + chunk * TN;

    // ---- stage Cs (fp16) ----
    #pragma unroll 1
    for (int i = tid; i < Kk*Dd; i += NTH)
        smh[CSH_OFF + (i >> 7)*STH + (i & 127)] = __float2half_rn(cw[i]);
    __syncthreads();
    {
        int k = tid >> 3, s8 = tid & 7;
        float part = 0.f;
        #pragma unroll
        for (int j = 0; j < 16; j++) {
            float c = __half2float(smh[CSH_OFF + k*STH + s8*16 + j]);
            part += c*c;
        }
        smf[RED_OFF + tid] = part;
    }
    __syncthreads();
    if (tid < Kk) {
        float s = 0.f;
        #pragma unroll
        for (int j = 0; j < 8; j++) s += smf[RED_OFF + tid*8 + j];
        smf[C2S_OFF + tid] = s;
    }
    __syncthreads();

    float c2v[4][2], scv[4][2];
    #pragma unroll
    for (int kt = 0; kt < 4; kt++)
        #pragma unroll
        for (int j = 0; j < 2; j++) {
            int k = 8*kt + 2*lc + j;
            c2v[kt][j] = smf[C2S_OFF + k];
            scv[kt][j] = scale[k];
        }

    const int rowA  = 16*w + lr;
    const int dwarp = 16*w;

    // per-thread ldmatrix base addresses (bytes, shared space)
    const int lrow8 = (l & 7) + ((l & 8) ? 8 : 0);      // row-in-16 for A-frags
    const int lcol8 = (l & 16) ? 8 : 0;                 // col-half for A-frags
    const unsigned aA1 = sptr(&smh[XSH_OFF + (16*w + lrow8)*STH + lcol8]);
    const unsigned aB1 = sptr(&smh[CSH_OFF + ((l & 7) + 8*((l >> 4) & 1))*STH
                                   + ((l & 8) ? 8 : 0)]);
    const unsigned aA2 = sptr(&smh[ASH_OFF + lrow8*STH + lcol8]);
    const unsigned aB2 = sptr(&smh[XSH_OFF + ((l & 7) + 8*((l >> 3) & 1))*STH
                                   + dwarp + 8*(l >> 4)]);

    float D2[2][2][4];
    #pragma unroll
    for (int mt = 0; mt < 2; mt++)
        #pragma unroll
        for (int nt = 0; nt < 2; nt++)
            #pragma unroll
            for (int r = 0; r < 4; r++) D2[mt][nt][r] = 0.f;
    float asum_acc = 0.f;            // valid in tid<32

    for (int t = 0; t < NT; t++) {
        __syncthreads();

        // ---- fill Xs (fp16, n-major only) + exact-fp32 x2 partials ----
        {
            const int nl = tid & 31, dq = tid >> 5;
            #pragma unroll
            for (int p = 0; p < 4; p++) {
                const int n = p*32 + nl;
                const float* src = xb + (size_t)(dq*16)*HWn + t*TIN + n;
                __half2 h[8];
                float part = 0.f;
                #pragma unroll
                for (int j = 0; j < 4; j++) {
                    float v0 = src[(size_t)(4*j+0)*HWn];
                    float v1 = src[(size_t)(4*j+1)*HWn];
                    float v2 = src[(size_t)(4*j+2)*HWn];
                    float v3 = src[(size_t)(4*j+3)*HWn];
                    part += v0*v0 + v1*v1 + v2*v2 + v3*v3;
                    h[2*j]   = __floats2half2_rn(v0, v1);
                    h[2*j+1] = __floats2half2_rn(v2, v3);
                }
                *(uint4*)&smh[XSH_OFF + n*STH + dq*16]     = *(uint4*)&h[0];
                *(uint4*)&smh[XSH_OFF + n*STH + dq*16 + 8] = *(uint4*)&h[4];
                smf[X2P_OFF + dq*128 + n] = part;
            }
        }
        __syncthreads();   // Xs + X2P complete

        // ---- GEMM1: xc[n,k]  (8 d-steps; A 1x ldm4, B 2x ldm4) ----
        float D1[4][4];
        #pragma unroll
        for (int kt = 0; kt < 4; kt++)
            #pragma unroll
            for (int r = 0; r < 4; r++) D1[kt][r] = 0.f;
        #pragma unroll 4
        for (int ds = 0; ds < 8; ds++) {
            const unsigned doff = ds*32;           // 16 halves
            unsigned a0, a1, a2, a3;
            ldm4(a0, a1, a2, a3, aA1 + doff);
            unsigned b00, b01, b10, b11;
            ldm4(b00, b01, b10, b11, aB1 + doff);                 // kt0 (r0,r1), kt1 (r2,r3)
            mma_f16(D1[0], a0, a1, a2, a3, b00, b01);
            mma_f16(D1[1], a0, a1, a2, a3, b10, b11);
            ldm4(b00, b01, b10, b11, aB1 + 16*STH*2 + doff);      // kt2, kt3
            mma_f16(D1[2], a0, a1, a2, a3, b00, b01);
            mma_f16(D1[3], a0, a1, a2, a3, b10, b11);
        }

        // ---- softmax (x2 from X2P) + As(fp16) + shuffle asum ----
        {
            float x2_0 = 0.f, x2_1 = 0.f;
            #pragma unroll
            for (int dq = 0; dq < 8; dq++) {
                x2_0 += smf[X2P_OFF + dq*128 + rowA];
                x2_1 += smf[X2P_OFF + dq*128 + rowA + 8];
            }
            float sl[4][4];
            #pragma unroll
            for (int kt = 0; kt < 4; kt++) {
                sl[kt][0] = scv[kt][0]*(x2_0 - 2.f*D1[kt][0] + c2v[kt][0]);
                sl[kt][1] = scv[kt][1]*(x2_0 - 2.f*D1[kt][1] + c2v[kt][1]);
                sl[kt][2] = scv[kt][0]*(x2_1 - 2.f*D1[kt][2] + c2v[kt][0]);
                sl[kt][3] = scv[kt][1]*(x2_1 - 2.f*D1[kt][3] + c2v[kt][1]);
            }
            float m0 = -3.4e38f, m1 = -3.4e38f;
            #pragma unroll
            for (int kt = 0; kt < 4; kt++) {
                m0 = fmaxf(m0, fmaxf(sl[kt][0], sl[kt][1]));
                m1 = fmaxf(m1, fmaxf(sl[kt][2], sl[kt][3]));
            }
            m0 = fmaxf(m0, __shfl_xor_sync(~0u, m0, 1));
            m0 = fmaxf(m0, __shfl_xor_sync(~0u, m0, 2));
            m1 = fmaxf(m1, __shfl_xor_sync(~0u, m1, 1));
            m1 = fmaxf(m1, __shfl_xor_sync(~0u, m1, 2));
            float s0 = 0.f, s1 = 0.f;
            #pragma unroll
            for (int kt = 0; kt < 4; kt++) {
                sl[kt][0] = __expf(sl[kt][0] - m0); s0 += sl[kt][0];
                sl[kt][1] = __expf(sl[kt][1] - m0); s0 += sl[kt][1];
                sl[kt][2] = __expf(sl[kt][2] - m1); s1 += sl[kt][2];
                sl[kt][3] = __expf(sl[kt][3] - m1); s1 += sl[kt][3];
            }
            s0 += __shfl_xor_sync(~0u, s0, 1); s0 += __shfl_xor_sync(~0u, s0, 2);
            s1 += __shfl_xor_sync(~0u, s1, 1); s1 += __shfl_xor_sync(~0u, s1, 2);
            const float i0 = 1.f/s0, i1 = 1.f/s1;
            float aw[4][2];
            #pragma unroll
            for (int kt = 0; kt < 4; kt++)
                #pragma unroll
                for (int j = 0; j < 2; j++) {
                    int k = 8*kt + 2*lc + j;
                    __half h0 = __float2half_rn(sl[kt][j]*i0);
                    __half h1 = __float2half_rn(sl[kt][2+j]*i1);
                    smh[ASH_OFF + k*STH + rowA]     = h0;
                    smh[ASH_OFF + k*STH + rowA + 8] = h1;
                    aw[kt][j] = __half2float(h0) + __half2float(h1);
                }
            #pragma unroll
            for (int kt = 0; kt < 4; kt++)
                #pragma unroll
                for (int j = 0; j < 2; j++) {
                    float v = aw[kt][j];
                    v += __shfl_xor_sync(~0u, v, 4);
                    v += __shfl_xor_sync(~0u, v, 8);
                    v += __shfl_xor_sync(~0u, v, 16);
                    aw[kt][j] = v;
                }
            if (lr == 0) {
                #pragma unroll
                for (int kt = 0; kt < 4; kt++)
                    #pragma unroll
                    for (int j = 0; j < 2; j++)
                        smf[RED_OFF + w*32 + 8*kt + 2*lc + j] = aw[kt][j];
            }
        }
        __syncthreads();   // As + RED complete

        if (tid < Kk) {
            float s = 0.f;
            #pragma unroll
            for (int ww = 0; ww < 8; ww++) s += smf[RED_OFF + ww*32 + tid];
            asum_acc += s;
        }

        // ---- GEMM2: E[k,d] += A[k,n] X[n,d] (8 n-steps; B via ldm4 .trans) ----
        #pragma unroll 4
        for (int ns = 0; ns < 8; ns++) {
            const unsigned nrow = ns*16*STH*2;     // +16 n-rows (bytes)
            const unsigned ncol = ns*32;           // +16 n-cols in As (bytes)
            unsigned bx00, bx01, bx10, bx11;       // (nt0 b0,b1), (nt1 b0,b1)
            ldm4t(bx00, bx01, bx10, bx11, aB2 + nrow);
            #pragma unroll
            for (int mt = 0; mt < 2; mt++) {
                unsigned a0, a1, a2, a3;
                ldm4(a0, a1, a2, a3, aA2 + mt*16*STH*2 + ncol);
                mma_f16(D2[mt][0], a0, a1, a2, a3, bx00, bx01);
                mma_f16(D2[mt][1], a0, a1, a2, a3, bx10, bx11);
            }
        }
    }

    // ---- ASUM publish + epilogue (fp16 scratch) ----
    if (tid < Kk) smf[ASUM_OFF + tid] = asum_acc;
    __syncthreads();
    {
        const size_t planeH2 = (size_t)(b*CH + chunk)*(Kk*Dd/2);
        #pragma unroll
        for (int mt = 0; mt < 2; mt++) {
            const int k0 = 16*mt + lr;
            const float as0 = smf[ASUM_OFF + k0];
            const float as1 = smf[ASUM_OFF + k0 + 8];
            #pragma unroll
            for (int nt = 0; nt < 2; nt++) {
                const int dc = dwarp + 8*nt + 2*lc;
                float c00 = __half2float(smh[CSH_OFF + k0*STH + dc]);
                float c01 = __half2float(smh[CSH_OFF + k0*STH + dc + 1]);
                float c10 = __half2float(smh[CSH_OFF + (k0+8)*STH + dc]);
                float c11 = __half2float(smh[CSH_OFF + (k0+8)*STH + dc + 1]);
                g_scratchH[planeH2 + ((k0*Dd + dc) >> 1)] =
                    __floats2half2_rn(D2[mt][nt][0] - as0*c00, D2[mt][nt][1] - as0*c01);
                g_scratchH[planeH2 + (((k0+8)*Dd + dc) >> 1)] =
                    __floats2half2_rn(D2[mt][nt][2] - as1*c10, D2[mt][nt][3] - as1*c11);
            }
        }
    }
}

// reduce: PDL secondary, fixed-order fp32 tree (bitwise deterministic).
__global__ void __launch_bounds__(256) enc_reduce(float* __restrict__ out)
{
    cudaGridDependencySynchronize();
    __shared__ float4 red[256][2];
    const int tid = threadIdx.x;
    const int o   = tid & 15;
    const int c   = tid >> 4;
    const int u   = blockIdx.x*16 + o;        // unit of 8 floats, 0..8191
    const int b   = u >> 9;
    const int j   = u & 511;
    uint4 v = ((const uint4*)g_scratchH)[((size_t)b*CH + c)*512 + j];
    {
        float2 f0 = __half22float2(*(__half2*)&v.x);
        float2 f1 = __half22float2(*(__half2*)&v.y);
        float2 f2 = __half22float2(*(__half2*)&v.z);
        float2 f3 = __half22float2(*(__half2*)&v.w);
        red[tid][0] = make_float4(f0.x, f0.y, f1.x, f1.y);
        red[tid][1] = make_float4(f2.x, f2.y, f3.x, f3.y);
    }
    __syncthreads();
    if (tid < 64) {
        #pragma unroll
        for (int h = 0; h < 2; h++) {
            float4 a = red[tid][h], bb = red[tid+64][h],
                   cc = red[tid+128][h], d = red[tid+192][h];
            float4 s;
            s.x = (a.x + bb.x) + (cc.x + d.x);
            s.y = (a.y + bb.y) + (cc.y + d.y);
            s.z = (a.z + bb.z) + (cc.z + d.z);
            s.w = (a.w + bb.w) + (cc.w + d.w);
            red[tid][h] = s;
        }
    }
    __syncthreads();
    if (tid < 16) {
        float4* outp = (float4*)out + (size_t)u*2;
        #pragma unroll
        for (int h = 0; h < 2; h++) {
            float4 a = red[tid][h], bb = red[tid+16][h],
                   cc = red[tid+32][h], d = red[tid+48][h];
            float4 r;
            r.x = (a.x + bb.x) + (cc.x + d.x);
            r.y = (a.y + bb.y) + (cc.y + d.y);
            r.z = (a.z + bb.z) + (cc.z + d.z);
            r.w = (a.w + bb.w) + (cc.w + d.w);
            outp[h] = r;
        }
    }
}

extern "C" void kernel_launch(void* const* d_in, const int* in_sizes, int n_in,
                              void* d_out, int out_size)
{
    const float* x  = (const float*)d_in[0];
    const float* cw = (const float*)d_in[1];
    const float* sc = (const float*)d_in[2];
    float* out = (float*)d_out;

    cudaFuncSetAttribute(enc_main, cudaFuncAttributeMaxDynamicSharedMemorySize, SM_BYTES);
    enc_main<<<dim3(CH, Bb), NTH, SM_BYTES>>>(x, cw, sc);

    cudaLaunchConfig_t cfg = {};
    cfg.gridDim  = dim3(512, 1, 1);
    cfg.blockDim = dim3(256, 1, 1);
    cfg.dynamicSmemBytes = 0;
    cfg.stream = 0;
    cudaLaunchAttribute attrs[1];
    attrs[0].id = cudaLaunchAttributeProgrammaticStreamSerialization;
    attrs[0].val.programmaticStreamSerializationAllowed = 1;
    cfg.attrs = attrs;
    cfg.numAttrs = 1;
    cudaLaunchKernelEx(&cfg, enc_reduce, out);
}

// round 17
// speedup vs baseline: 1.1774x; 1.1774x over previous
#include <cuda_runtime.h>
#include <cuda_fp16.h>

// Encoding layer, fp16 tensor cores (mma.m16n8k16) + ldmatrix fragment loads.
// B=16, D=128, N=4096, K=32. One CTA = one (b, chunk) tile of 128 n.
// 512-CTA grid, ~57.4KB smem -> 3 CTAs/SM resident (grid-limited occ fixed).
// Single n-major X layout; GEMM2-B via ldmatrix.trans (no transposed copy).
// fp16 scratch partials; PDL reduce over 32 chunks, fixed order (determ.).

#define Dd   128
#define Kk   32
#define Bb   16
#define HWn  4096
#define TN   128
#define CH   32          // 4096 / TN
#define NTH  256
#define STH  136         // half-stride per row (272 B; rows cycle all 8 16B-groups)

#define XSH_OFF  0                       // [128][STH] n-major
#define CSH_OFF  (128*STH)               // [32][STH]
#define ASH_OFF  (160*STH)               // [32][STH]
#define HALF_TOT (192*STH)
#define X2P_OFF  0                       // floats: [8][128]
#define C2S_OFF  1024
#define RED_OFF  (C2S_OFF + 32)
#define ASUM_OFF (RED_OFF + 256)
#define FLT_TOT  (ASUM_OFF + 32)
#define SM_BYTES (HALF_TOT*2 + FLT_TOT*4)

__device__ __half2 g_scratchH[(size_t)Bb*CH*Kk*Dd/2];   // 4 MB fp16 partials

__device__ __forceinline__ void mma_f16(float* d,
    unsigned a0, unsigned a1, unsigned a2, unsigned a3, unsigned b0, unsigned b1) {
    asm("mma.sync.aligned.m16n8k16.row.col.f32.f16.f16.f32 "
        "{%0,%1,%2,%3}, {%4,%5,%6,%7}, {%8,%9}, {%0,%1,%2,%3};"
        : "+f"(d[0]), "+f"(d[1]), "+f"(d[2]), "+f"(d[3])
        : "r"(a0), "r"(a1), "r"(a2), "r"(a3), "r"(b0), "r"(b1));
}
__device__ __forceinline__ unsigned sptr(const void* p) {
    return (unsigned)__cvta_generic_to_shared(p);
}
__device__ __forceinline__ void ldm4(unsigned& r0, unsigned& r1,
                                     unsigned& r2, unsigned& r3, unsigned a) {
    asm volatile("ldmatrix.sync.aligned.m8n8.x4.shared.b16 {%0,%1,%2,%3}, [%4];"
                 : "=r"(r0), "=r"(r1), "=r"(r2), "=r"(r3) : "r"(a));
}
__device__ __forceinline__ void ldm4t(unsigned& r0, unsigned& r1,
                                      unsigned& r2, unsigned& r3, unsigned a) {
    asm volatile("ldmatrix.sync.aligned.m8n8.x4.trans.shared.b16 {%0,%1,%2,%3}, [%4];"
                 : "=r"(r0), "=r"(r1), "=r"(r2), "=r"(r3) : "r"(a));
}

__global__ void __launch_bounds__(NTH, 3) enc_main(
    const float* __restrict__ x,      // (B, D, HWn)
    const float* __restrict__ cw,     // (K, D)
    const float* __restrict__ scale)  // (K,)
{
    extern __shared__ __align__(16) char smraw[];
    __half* smh = (__half*)smraw;
    float*  smf = (float*)(smraw + HALF_TOT*2);

    const int tid = threadIdx.x;
    const int w   = tid >> 5;
    const int l   = tid & 31;
    const int lr  = l >> 2;
    const int lc  = l & 3;
    const int b     = blockIdx.y;
    const int chunk = blockIdx.x;
    const float* xb = x + (size_t)b * Dd * HWn + chunk * TN;

    // ---- stage Cs (fp16) ----
    #pragma unroll 1
    for (int i = tid; i < Kk*Dd; i += NTH)
        smh[CSH_OFF + (i >> 7)*STH + (i & 127)] = __float2half_rn(cw[i]);
    __syncthreads();
    {
        int k = tid >> 3, s8 = tid & 7;
        float part = 0.f;
        #pragma unroll
        for (int j = 0; j < 16; j++) {
            float c = __half2float(smh[CSH_OFF + k*STH + s8*16 + j]);
            part += c*c;
        }
        smf[RED_OFF + tid] = part;
    }
    __syncthreads();
    if (tid < Kk) {
        float s = 0.f;
        #pragma unroll
        for (int j = 0; j < 8; j++) s += smf[RED_OFF + tid*8 + j];
        smf[C2S_OFF + tid] = s;
    }

    // ---- fill Xs (fp16, n-major) + exact-fp32 x2 partials ----
    {
        const int nl = tid & 31, dq = tid >> 5;
        #pragma unroll
        for (int p = 0; p < 4; p++) {
            const int n = p*32 + nl;
            const float* src = xb + (size_t)(dq*16)*HWn + n;
            __half2 h[8];
            float part = 0.f;
            #pragma unroll
            for (int j = 0; j < 4; j++) {
                float v0 = src[(size_t)(4*j+0)*HWn];
                float v1 = src[(size_t)(4*j+1)*HWn];
                float v2 = src[(size_t)(4*j+2)*HWn];
                float v3 = src[(size_t)(4*j+3)*HWn];
                part += v0*v0 + v1*v1 + v2*v2 + v3*v3;
                h[2*j]   = __floats2half2_rn(v0, v1);
                h[2*j+1] = __floats2half2_rn(v2, v3);
            }
            *(uint4*)&smh[XSH_OFF + n*STH + dq*16]     = *(uint4*)&h[0];
            *(uint4*)&smh[XSH_OFF + n*STH + dq*16 + 8] = *(uint4*)&h[4];
            smf[X2P_OFF + dq*128 + n] = part;
        }
    }
    __syncthreads();   // Cs + C2S + Xs + X2P complete

    float c2v[4][2], scv[4][2];
    #pragma unroll
    for (int kt = 0; kt < 4; kt++)
        #pragma unroll
        for (int j = 0; j < 2; j++) {
            int k = 8*kt + 2*lc + j;
            c2v[kt][j] = smf[C2S_OFF + k];
            scv[kt][j] = scale[k];
        }

    const int rowA  = 16*w + lr;
    const int dwarp = 16*w;

    // per-thread ldmatrix base addresses (bytes, shared space)
    const int lrow8 = (l & 7) + ((l & 8) ? 8 : 0);
    const int lcol8 = (l & 16) ? 8 : 0;
    const unsigned aA1 = sptr(&smh[XSH_OFF + (16*w + lrow8)*STH + lcol8]);
    const unsigned aB1 = sptr(&smh[CSH_OFF + ((l & 7) + 8*((l >> 4) & 1))*STH
                                   + ((l & 8) ? 8 : 0)]);
    const unsigned aA2 = sptr(&smh[ASH_OFF + lrow8*STH + lcol8]);
    const unsigned aB2 = sptr(&smh[XSH_OFF + ((l & 7) + 8*((l >> 3) & 1))*STH
                                   + dwarp + 8*(l >> 4)]);

    // ---- GEMM1: xc[n,k] ----
    float D1[4][4];
    #pragma unroll
    for (int kt = 0; kt < 4; kt++)
        #pragma unroll
        for (int r = 0; r < 4; r++) D1[kt][r] = 0.f;
    #pragma unroll 4
    for (int ds = 0; ds < 8; ds++) {
        const unsigned doff = ds*32;
        unsigned a0, a1, a2, a3;
        ldm4(a0, a1, a2, a3, aA1 + doff);
        unsigned b00, b01, b10, b11;
        ldm4(b00, b01, b10, b11, aB1 + doff);
        mma_f16(D1[0], a0, a1, a2, a3, b00, b01);
        mma_f16(D1[1], a0, a1, a2, a3, b10, b11);
        ldm4(b00, b01, b10, b11, aB1 + 16*STH*2 + doff);
        mma_f16(D1[2], a0, a1, a2, a3, b00, b01);
        mma_f16(D1[3], a0, a1, a2, a3, b10, b11);
    }

    // ---- softmax + As(fp16) + shuffle asum ----
    {
        float x2_0 = 0.f, x2_1 = 0.f;
        #pragma unroll
        for (int dq = 0; dq < 8; dq++) {
            x2_0 += smf[X2P_OFF + dq*128 + rowA];
            x2_1 += smf[X2P_OFF + dq*128 + rowA + 8];
        }
        float sl[4][4];
        #pragma unroll
        for (int kt = 0; kt < 4; kt++) {
            sl[kt][0] = scv[kt][0]*(x2_0 - 2.f*D1[kt][0] + c2v[kt][0]);
            sl[kt][1] = scv[kt][1]*(x2_0 - 2.f*D1[kt][1] + c2v[kt][1]);
            sl[kt][2] = scv[kt][0]*(x2_1 - 2.f*D1[kt][2] + c2v[kt][0]);
            sl[kt][3] = scv[kt][1]*(x2_1 - 2.f*D1[kt][3] + c2v[kt][1]);
        }
        float m0 = -3.4e38f, m1 = -3.4e38f;
        #pragma unroll
        for (int kt = 0; kt < 4; kt++) {
            m0 = fmaxf(m0, fmaxf(sl[kt][0], sl[kt][1]));
            m1 = fmaxf(m1, fmaxf(sl[kt][2], sl[kt][3]));
        }
        m0 = fmaxf(m0, __shfl_xor_sync(~0u, m0, 1));
        m0 = fmaxf(m0, __shfl_xor_sync(~0u, m0, 2));
        m1 = fmaxf(m1, __shfl_xor_sync(~0u, m1, 1));
        m1 = fmaxf(m1, __shfl_xor_sync(~0u, m1, 2));
        float s0 = 0.f, s1 = 0.f;
        #pragma unroll
        for (int kt = 0; kt < 4; kt++) {
            sl[kt][0] = __expf(sl[kt][0] - m0); s0 += sl[kt][0];
            sl[kt][1] = __expf(sl[kt][1] - m0); s0 += sl[kt][1];
            sl[kt][2] = __expf(sl[kt][2] - m1); s1 += sl[kt][2];
            sl[kt][3] = __expf(sl[kt][3] - m1); s1 += sl[kt][3];
        }
        s0 += __shfl_xor_sync(~0u, s0, 1); s0 += __shfl_xor_sync(~0u, s0, 2);
        s1 += __shfl_xor_sync(~0u, s1, 1); s1 += __shfl_xor_sync(~0u, s1, 2);
        const float i0 = 1.f/s0, i1 = 1.f/s1;
        float aw[4][2];
        #pragma unroll
        for (int kt = 0; kt < 4; kt++)
            #pragma unroll
            for (int j = 0; j < 2; j++) {
                int k = 8*kt + 2*lc + j;
                __half h0 = __float2half_rn(sl[kt][j]*i0);
                __half h1 = __float2half_rn(sl[kt][2+j]*i1);
                smh[ASH_OFF + k*STH + rowA]     = h0;
                smh[ASH_OFF + k*STH + rowA + 8] = h1;
                aw[kt][j] = __half2float(h0) + __half2float(h1);
            }
        #pragma unroll
        for (int kt = 0; kt < 4; kt++)
            #pragma unroll
            for (int j = 0; j < 2; j++) {
                float v = aw[kt][j];
                v += __shfl_xor_sync(~0u, v, 4);
                v += __shfl_xor_sync(~0u, v, 8);
                v += __shfl_xor_sync(~0u, v, 16);
                aw[kt][j] = v;
            }
        if (lr == 0) {
            #pragma unroll
            for (int kt = 0; kt < 4; kt++)
                #pragma unroll
                for (int j = 0; j < 2; j++)
                    smf[RED_OFF + w*32 + 8*kt + 2*lc + j] = aw[kt][j];
        }
    }
    __syncthreads();   // As + RED complete

    float asum_acc = 0.f;
    if (tid < Kk) {
        #pragma unroll
        for (int ww = 0; ww < 8; ww++) asum_acc += smf[RED_OFF + ww*32 + tid];
    }

    // ---- GEMM2: E[k,d] = A[k,n] X[n,d] ----
    float D2[2][2][4];
    #pragma unroll
    for (int mt = 0; mt < 2; mt++)
        #pragma unroll
        for (int nt = 0; nt < 2; nt++)
            #pragma unroll
            for (int r = 0; r < 4; r++) D2[mt][nt][r] = 0.f;
    #pragma unroll 4
    for (int ns = 0; ns < 8; ns++) {
        const unsigned nrow = ns*16*STH*2;
        const unsigned ncol = ns*32;
        unsigned bx00, bx01, bx10, bx11;
        ldm4t(bx00, bx01, bx10, bx11, aB2 + nrow);
        #pragma unroll
        for (int mt = 0; mt < 2; mt++) {
            unsigned a0, a1, a2, a3;
            ldm4(a0, a1, a2, a3, aA2 + mt*16*STH*2 + ncol);
            mma_f16(D2[mt][0], a0, a1, a2, a3, bx00, bx01);
            mma_f16(D2[mt][1], a0, a1, a2, a3, bx10, bx11);
        }
    }

    // ---- ASUM publish + epilogue (fp16 scratch) ----
    if (tid < Kk) smf[ASUM_OFF + tid] = asum_acc;
    __syncthreads();
    {
        const size_t planeH2 = (size_t)(b*CH + chunk)*(Kk*Dd/2);
        #pragma unroll
        for (int mt = 0; mt < 2; mt++) {
            const int k0 = 16*mt + lr;
            const float as0 = smf[ASUM_OFF + k0];
            const float as1 = smf[ASUM_OFF + k0 + 8];
            #pragma unroll
            for (int nt = 0; nt < 2; nt++) {
                const int dc = dwarp + 8*nt + 2*lc;
                float c00 = __half2float(smh[CSH_OFF + k0*STH + dc]);
                float c01 = __half2float(smh[CSH_OFF + k0*STH + dc + 1]);
                float c10 = __half2float(smh[CSH_OFF + (k0+8)*STH + dc]);
                float c11 = __half2float(smh[CSH_OFF + (k0+8)*STH + dc + 1]);
                g_scratchH[planeH2 + ((k0*Dd + dc) >> 1)] =
                    __floats2half2_rn(D2[mt][nt][0] - as0*c00, D2[mt][nt][1] - as0*c01);
                g_scratchH[planeH2 + (((k0+8)*Dd + dc) >> 1)] =
                    __floats2half2_rn(D2[mt][nt][2] - as1*c10, D2[mt][nt][3] - as1*c11);
            }
        }
    }
}

// reduce: PDL secondary; block = 8 output units x 32 chunks, one load/thread,
// fixed-order fp32 tree (bitwise deterministic).
__global__ void __launch_bounds__(256) enc_reduce(float* __restrict__ out)
{
    cudaGridDependencySynchronize();
    __shared__ float4 red[256][2];
    const int tid = threadIdx.x;
    const int o   = tid & 7;                  // unit within block
    const int c   = tid >> 3;                 // chunk 0..31
    const int u   = blockIdx.x*8 + o;         // unit of 8 floats, 0..8191
    const int b   = u >> 9;                   // 512 units per batch plane
    const int j   = u & 511;
    uint4 v = ((const uint4*)g_scratchH)[((size_t)b*CH + c)*512 + j];
    {
        float2 f0 = __half22float2(*(__half2*)&v.x);
        float2 f1 = __half22float2(*(__half2*)&v.y);
        float2 f2 = __half22float2(*(__half2*)&v.z);
        float2 f3 = __half22float2(*(__half2*)&v.w);
        red[tid][0] = make_float4(f0.x, f0.y, f1.x, f1.y);
        red[tid][1] = make_float4(f2.x, f2.y, f3.x, f3.y);
    }
    __syncthreads();
    if (tid < 64) {    // fold chunks {c, c+8, c+16, c+24}
        #pragma unroll
        for (int h = 0; h < 2; h++) {
            float4 a = red[tid][h], bb = red[tid+64][h],
                   cc = red[tid+128][h], d = red[tid+192][h];
            float4 s;
            s.x = (a.x + bb.x) + (cc.x + d.x);
            s.y = (a.y + bb.y) + (cc.y + d.y);
            s.z = (a.z + bb.z) + (cc.z + d.z);
            s.w = (a.w + bb.w) + (cc.w + d.w);
            red[tid][h] = s;
        }
    }
    __syncthreads();
    if (tid < 8) {     // fold remaining 8 chunk-groups, fixed order
        float4* outp = (float4*)out + (size_t)u*2;
        #pragma unroll
        for (int h = 0; h < 2; h++) {
            float4 r = red[tid][h];
            #pragma unroll
            for (int q = 1; q < 8; q++) {
                float4 v2 = red[tid + 8*q][h];
                r.x += v2.x; r.y += v2.y; r.z += v2.z; r.w += v2.w;
            }
            outp[h] = r;
        }
    }
}

extern "C" void kernel_launch(void* const* d_in, const int* in_sizes, int n_in,
                              void* d_out, int out_size)
{
    const float* x  = (const float*)d_in[0];
    const float* cw = (const float*)d_in[1];
    const float* sc = (const float*)d_in[2];
    float* out = (float*)d_out;

    cudaFuncSetAttribute(enc_main, cudaFuncAttributeMaxDynamicSharedMemorySize, SM_BYTES);
    enc_main<<<dim3(CH, Bb), NTH, SM_BYTES>>>(x, cw, sc);

    cudaLaunchConfig_t cfg = {};
    cfg.gridDim  = dim3(1024, 1, 1);
    cfg.blockDim = dim3(256, 1, 1);
    cfg.dynamicSmemBytes = 0;
    cfg.stream = 0;
    cudaLaunchAttribute attrs[1];
    attrs[0].id = cudaLaunchAttributeProgrammaticStreamSerialization;
    attrs[0].val.programmaticStreamSerializationAllowed = 1;
    cfg.attrs = attrs;
    cfg.numAttrs = 1;
    cudaLaunchKernelEx(&cfg, enc_reduce, out);
}